// round 2
// baseline (speedup 1.0000x reference)
#include <cuda_runtime.h>
#include <cuda_bf16.h>
#include <cstdint>

#define D_MODEL 256
#define NB 16
#define ACT_OFF 10
#define LN_EPS 1e-5f
#define THREADS 256
#define GROUPS 4            // 64-thread groups per block
#define TOK_PER_GROUP 8     // tokens each group processes
#define TOK_PER_BLOCK (GROUPS * TOK_PER_GROUP)  // 32

__global__ __launch_bounds__(THREADS, 2)
void action_embedding_kernel(
    const int*   __restrict__ token_ids,     // [N]
    const int*   __restrict__ action_actors, // [N]
    const int*   __restrict__ action_streets,// [N]
    const float* __restrict__ legal_masks,   // [N, 16]
    const float* __restrict__ actor_emb,     // [2, 256]
    const float* __restrict__ street_emb,    // [4, 256]
    const float* __restrict__ type_emb,      // [16, 256]
    const float* __restrict__ mlp_w,         // [16, 256]
    const float* __restrict__ mlp_b,         // [256]
    const float* __restrict__ ln_gamma,      // [256]
    const float* __restrict__ ln_beta,       // [256]
    float*       __restrict__ out,           // [N, 256]
    int n_tok)
{
    // [parity][group][warp_in_group][{sum,sq}]
    __shared__ float stats[2][GROUPS][2][2];

    const int tid  = threadIdx.x;
    const int g    = tid >> 6;        // group 0..3
    const int u    = tid & 63;        // thread within group
    const int wig  = (tid >> 5) & 1;  // warp within group
    const int lane = tid & 31;
    const int d0   = 4 * u;           // this thread's channel base (0..252)

    // ---- persistent per-thread state: W column slice + LN params + bias ----
    float4 W[NB];
    #pragma unroll
    for (int k = 0; k < NB; k++)
        W[k] = __ldg(reinterpret_cast<const float4*>(mlp_w + k * D_MODEL + d0));
    const float4 bias = __ldg(reinterpret_cast<const float4*>(mlp_b    + d0));
    const float4 ga   = __ldg(reinterpret_cast<const float4*>(ln_gamma + d0));
    const float4 be   = __ldg(reinterpret_cast<const float4*>(ln_beta  + d0));

    const long t_base = (long)blockIdx.x * TOK_PER_BLOCK + (long)g * TOK_PER_GROUP;

    #pragma unroll
    for (int it = 0; it < TOK_PER_GROUP; it++) {
        const long t = t_base + it;
        const bool valid = (t < n_tok);
        const int p = it & 1;

        int tk = 0;
        if (valid) tk = __ldg(token_ids + t);
        const bool active = valid && (tk >= ACT_OFF) && (tk < ACT_OFF + NB);

        float4 acc = bias;
        if (active) {
            // 16 mask values, broadcast across the warp (L1-broadcast LDG.128)
            float m[NB];
            const float4* lm4 = reinterpret_cast<const float4*>(legal_masks + t * NB);
            #pragma unroll
            for (int i = 0; i < 4; i++) {
                float4 v = __ldg(lm4 + i);
                m[4*i+0] = v.x; m[4*i+1] = v.y; m[4*i+2] = v.z; m[4*i+3] = v.w;
            }
            #pragma unroll
            for (int k = 0; k < NB; k++) {
                acc.x = fmaf(m[k], W[k].x, acc.x);
                acc.y = fmaf(m[k], W[k].y, acc.y);
                acc.z = fmaf(m[k], W[k].z, acc.z);
                acc.w = fmaf(m[k], W[k].w, acc.w);
            }
            // partial LN stats over this thread's 4 channels
            float s = acc.x + acc.y + acc.z + acc.w;
            float q = fmaf(acc.x, acc.x,
                      fmaf(acc.y, acc.y,
                      fmaf(acc.z, acc.z, acc.w * acc.w)));
            #pragma unroll
            for (int o = 16; o > 0; o >>= 1) {
                s += __shfl_xor_sync(0xFFFFFFFFu, s, o);
                q += __shfl_xor_sync(0xFFFFFFFFu, q, o);
            }
            if (lane == 0) { stats[p][g][wig][0] = s; stats[p][g][wig][1] = q; }
        }

        __syncthreads();  // uniform across the block; double-buffered stats

        if (valid) {
            float4* dst = reinterpret_cast<float4*>(out + t * D_MODEL) + u;
            if (active) {
                const float sum = stats[p][g][0][0] + stats[p][g][1][0];
                const float sq  = stats[p][g][0][1] + stats[p][g][1][1];
                const float inv_d = 1.0f / 256.0f;
                const float mu  = sum * inv_d;
                const float var = fmaf(sq, inv_d, -mu * mu);
                const float rs  = rsqrtf(var + LN_EPS);

                int a = __ldg(action_actors + t);  a = a < 0 ? 0 : (a > 1 ? 1 : a);
                int s2 = __ldg(action_streets + t); s2 = s2 < 0 ? 0 : (s2 > 3 ? 3 : s2);
                const int aid = tk - ACT_OFF;

                float4 ea = __ldg(reinterpret_cast<const float4*>(actor_emb  + a   * D_MODEL + d0));
                float4 es = __ldg(reinterpret_cast<const float4*>(street_emb + s2  * D_MODEL + d0));
                float4 et = __ldg(reinterpret_cast<const float4*>(type_emb   + aid * D_MODEL + d0));

                float4 r;
                r.x = fmaxf(fmaf((acc.x - mu) * rs, ga.x, be.x), 0.f) + ea.x + es.x + et.x;
                r.y = fmaxf(fmaf((acc.y - mu) * rs, ga.y, be.y), 0.f) + ea.y + es.y + et.y;
                r.z = fmaxf(fmaf((acc.z - mu) * rs, ga.z, be.z), 0.f) + ea.z + es.z + et.z;
                r.w = fmaxf(fmaf((acc.w - mu) * rs, ga.w, be.w), 0.f) + ea.w + es.w + et.w;
                *dst = r;
            } else {
                *dst = make_float4(0.f, 0.f, 0.f, 0.f);
            }
        }
    }
}

extern "C" void kernel_launch(void* const* d_in, const int* in_sizes, int n_in,
                              void* d_out, int out_size)
{
    const int*   token_ids   = (const int*)  d_in[0];
    const int*   actors      = (const int*)  d_in[1];
    const int*   streets     = (const int*)  d_in[2];
    const float* legal_masks = (const float*)d_in[3];
    const float* actor_emb   = (const float*)d_in[4];
    const float* street_emb  = (const float*)d_in[5];
    const float* type_emb    = (const float*)d_in[6];
    const float* mlp_w       = (const float*)d_in[7];
    const float* mlp_b       = (const float*)d_in[8];
    const float* ln_gamma    = (const float*)d_in[9];
    const float* ln_beta     = (const float*)d_in[10];
    float* out = (float*)d_out;

    const int n_tok  = in_sizes[0];
    const int blocks = (n_tok + TOK_PER_BLOCK - 1) / TOK_PER_BLOCK;
    action_embedding_kernel<<<blocks, THREADS>>>(
        token_ids, actors, streets, legal_masks,
        actor_emb, street_emb, type_emb,
        mlp_w, mlp_b, ln_gamma, ln_beta,
        out, n_tok);
}

// round 3
// speedup vs baseline: 1.2174x; 1.2174x over previous
#include <cuda_runtime.h>
#include <cuda_bf16.h>
#include <cstdint>

#define D_MODEL 256
#define NB 16
#define ACT_OFF 10
#define LN_EPS 1e-5f
#define BT 64            // threads per block (2 warps = 1 group)
#define TPB 64           // tokens per block
#define PAIRS (TPB / 2)

struct PairSt {
    float4 acc0, acc1;
    int tk0, tk1, a0, s0, a1, s1;
    bool v0, v1, act0, act1;
};

__global__ __launch_bounds__(BT)
void action_embedding_kernel(
    const int*   __restrict__ token_ids,
    const int*   __restrict__ action_actors,
    const int*   __restrict__ action_streets,
    const float* __restrict__ legal_masks,
    const float* __restrict__ actor_emb,
    const float* __restrict__ street_emb,
    const float* __restrict__ type_emb,
    const float* __restrict__ mlp_w,
    const float* __restrict__ mlp_b,
    const float* __restrict__ ln_gamma,
    const float* __restrict__ ln_beta,
    float*       __restrict__ out,
    int n_tok)
{
    __shared__ float2 stats[2][2][2];   // [parity][tok_in_pair][warp]

    const int u    = threadIdx.x;       // 0..63, owns channels 4u..4u+3
    const int wig  = u >> 5;
    const int lane = u & 31;
    const int d0   = 4 * u;

    // ---- persistent registers: full W column slice + LN params ----
    float4 W[NB];
    #pragma unroll
    for (int k = 0; k < NB; k++)
        W[k] = __ldg(reinterpret_cast<const float4*>(mlp_w + k * D_MODEL + d0));
    const float4 bias = __ldg(reinterpret_cast<const float4*>(mlp_b    + d0));
    const float4 ga   = __ldg(reinterpret_cast<const float4*>(ln_gamma + d0));
    const float4 be   = __ldg(reinterpret_cast<const float4*>(ln_beta  + d0));

    const long base = (long)blockIdx.x * TPB;

    // ---- stage A: GEMM + warp-partial LN stats for pair i, write stats[p] ----
    auto stageA = [&](int i, int p) -> PairSt {
        PairSt st;
        const long t0 = base + 2 * i;
        const long t1 = t0 + 1;
        st.v0 = (t0 < n_tok); st.v1 = (t1 < n_tok);
        st.tk0 = st.v0 ? __ldg(token_ids + t0) : 0;
        st.tk1 = st.v1 ? __ldg(token_ids + t1) : 0;
        st.act0 = st.v0 && (st.tk0 >= ACT_OFF) && (st.tk0 < ACT_OFF + NB);
        st.act1 = st.v1 && (st.tk1 >= ACT_OFF) && (st.tk1 < ACT_OFF + NB);
        st.a0 = st.s0 = st.a1 = st.s1 = 0;
        if (st.act0) {   // uniform branch
            int a = __ldg(action_actors  + t0); st.a0 = a < 0 ? 0 : (a > 1 ? 1 : a);
            int s = __ldg(action_streets + t0); st.s0 = s < 0 ? 0 : (s > 3 ? 3 : s);
        }
        if (st.act1) {
            int a = __ldg(action_actors  + t1); st.a1 = a < 0 ? 0 : (a > 1 ? 1 : a);
            int s = __ldg(action_streets + t1); st.s1 = s < 0 ? 0 : (s > 3 ? 3 : s);
        }
        st.acc0 = bias; st.acc1 = bias;
        if (st.act0 | st.act1) {    // uniform
            // one coalesced 128B segment: lanes 0-15 -> t0's 16 masks, 16-31 -> t1's
            float mv = 0.f;
            const bool want = (lane < 16) ? st.act0 : st.act1;
            if (want) mv = __ldg(legal_masks + t0 * NB + lane);
            #pragma unroll
            for (int k = 0; k < NB; k++) {
                const float mk0 = __shfl_sync(0xFFFFFFFFu, mv, k);
                const float mk1 = __shfl_sync(0xFFFFFFFFu, mv, k + 16);
                st.acc0.x = fmaf(mk0, W[k].x, st.acc0.x);
                st.acc0.y = fmaf(mk0, W[k].y, st.acc0.y);
                st.acc0.z = fmaf(mk0, W[k].z, st.acc0.z);
                st.acc0.w = fmaf(mk0, W[k].w, st.acc0.w);
                st.acc1.x = fmaf(mk1, W[k].x, st.acc1.x);
                st.acc1.y = fmaf(mk1, W[k].y, st.acc1.y);
                st.acc1.z = fmaf(mk1, W[k].z, st.acc1.z);
                st.acc1.w = fmaf(mk1, W[k].w, st.acc1.w);
            }
            float s0 = st.acc0.x + st.acc0.y + st.acc0.z + st.acc0.w;
            float q0 = fmaf(st.acc0.x, st.acc0.x, fmaf(st.acc0.y, st.acc0.y,
                       fmaf(st.acc0.z, st.acc0.z, st.acc0.w * st.acc0.w)));
            float s1 = st.acc1.x + st.acc1.y + st.acc1.z + st.acc1.w;
            float q1 = fmaf(st.acc1.x, st.acc1.x, fmaf(st.acc1.y, st.acc1.y,
                       fmaf(st.acc1.z, st.acc1.z, st.acc1.w * st.acc1.w)));
            #pragma unroll
            for (int o = 16; o > 0; o >>= 1) {
                s0 += __shfl_xor_sync(0xFFFFFFFFu, s0, o);
                q0 += __shfl_xor_sync(0xFFFFFFFFu, q0, o);
                s1 += __shfl_xor_sync(0xFFFFFFFFu, s1, o);
                q1 += __shfl_xor_sync(0xFFFFFFFFu, q1, o);
            }
            if (lane == 0) {
                stats[p][0][wig] = make_float2(s0, q0);
                stats[p][1][wig] = make_float2(s1, q1);
            }
        }
        return st;
    };

    // ---- stage B: consume stats[p], embedding gathers, final store ----
    auto stageB = [&](int i, int p, const PairSt& st) {
        #pragma unroll
        for (int tok = 0; tok < 2; tok++) {
            const bool v = tok ? st.v1 : st.v0;
            if (!v) continue;   // uniform
            const long t = base + 2 * i + tok;
            float4* dst = reinterpret_cast<float4*>(out + t * D_MODEL) + u;
            const bool act = tok ? st.act1 : st.act0;
            if (act) {          // uniform
                const float2 sa = stats[p][tok][0];
                const float2 sb = stats[p][tok][1];
                const float inv = 1.0f / 256.0f;
                const float mu  = (sa.x + sb.x) * inv;
                const float var = fmaf(sa.y + sb.y, inv, -mu * mu);
                const float rs  = rsqrtf(var + LN_EPS);
                const int a   = tok ? st.a1 : st.a0;
                const int s   = tok ? st.s1 : st.s0;
                const int aid = (tok ? st.tk1 : st.tk0) - ACT_OFF;
                const float4 acc = tok ? st.acc1 : st.acc0;
                const float4 ea = __ldg(reinterpret_cast<const float4*>(actor_emb  + a   * D_MODEL + d0));
                const float4 es = __ldg(reinterpret_cast<const float4*>(street_emb + s   * D_MODEL + d0));
                const float4 et = __ldg(reinterpret_cast<const float4*>(type_emb   + aid * D_MODEL + d0));
                float4 r;
                r.x = fmaxf(fmaf((acc.x - mu) * rs, ga.x, be.x), 0.f) + ea.x + es.x + et.x;
                r.y = fmaxf(fmaf((acc.y - mu) * rs, ga.y, be.y), 0.f) + ea.y + es.y + et.y;
                r.z = fmaxf(fmaf((acc.z - mu) * rs, ga.z, be.z), 0.f) + ea.z + es.z + et.z;
                r.w = fmaxf(fmaf((acc.w - mu) * rs, ga.w, be.w), 0.f) + ea.w + es.w + et.w;
                *dst = r;
            } else {
                *dst = make_float4(0.f, 0.f, 0.f, 0.f);
            }
        }
    };

    // ---- pipelined main loop: one small-block barrier per 2 tokens ----
    PairSt cur = stageA(0, 0);
    __syncthreads();
    #pragma unroll 2
    for (int i = 0; i < PAIRS; i++) {
        const int p = i & 1;
        stageB(i, p, cur);                     // consumes stats[p] (pre-barrier writes)
        PairSt nxt = cur;
        if (i + 1 < PAIRS) nxt = stageA(i + 1, p ^ 1);   // writes stats[p^1]
        __syncthreads();                       // publishes stats[p^1]; fences reuse of stats[p]
        cur = nxt;
    }
}

extern "C" void kernel_launch(void* const* d_in, const int* in_sizes, int n_in,
                              void* d_out, int out_size)
{
    const int*   token_ids   = (const int*)  d_in[0];
    const int*   actors      = (const int*)  d_in[1];
    const int*   streets     = (const int*)  d_in[2];
    const float* legal_masks = (const float*)d_in[3];
    const float* actor_emb   = (const float*)d_in[4];
    const float* street_emb  = (const float*)d_in[5];
    const float* type_emb    = (const float*)d_in[6];
    const float* mlp_w       = (const float*)d_in[7];
    const float* mlp_b       = (const float*)d_in[8];
    const float* ln_gamma    = (const float*)d_in[9];
    const float* ln_beta     = (const float*)d_in[10];
    float* out = (float*)d_out;

    const int n_tok  = in_sizes[0];
    const int blocks = (n_tok + TPB - 1) / TPB;
    action_embedding_kernel<<<blocks, BT>>>(
        token_ids, actors, streets, legal_masks,
        actor_emb, street_emb, type_emb,
        mlp_w, mlp_b, ln_gamma, ln_beta,
        out, n_tok);
}

// round 5
// speedup vs baseline: 1.9711x; 1.6191x over previous
#include <cuda_runtime.h>
#include <cuda_bf16.h>
#include <cstdint>

#define D_MODEL 256
#define NB 16
#define ACT_OFF 10
#define LN_EPS 1e-5f
#define THREADS 128
#define WARPS 4
#define TPB 128     // tokens per block
#define GTOK 4      // active tokens processed together per warp

__global__ __launch_bounds__(THREADS)
void action_embedding_kernel(
    const int*   __restrict__ token_ids,
    const int*   __restrict__ action_actors,
    const int*   __restrict__ action_streets,
    const float* __restrict__ legal_masks,
    const float* __restrict__ actor_emb,
    const float* __restrict__ street_emb,
    const float* __restrict__ type_emb,
    const float* __restrict__ mlp_w,
    const float* __restrict__ mlp_b,
    const float* __restrict__ ln_gamma,
    const float* __restrict__ ln_beta,
    float*       __restrict__ out,
    int n_tok)
{
    __shared__ float Wsh[NB * D_MODEL];        // 16 KB
    __shared__ unsigned short alist[TPB];
    __shared__ unsigned short ilist[TPB];
    __shared__ int cnts[2];

    const int tid  = threadIdx.x;
    const int warp = tid >> 5;
    const int lane = tid & 31;
    const int d0   = 4 * lane;                 // channels d0..d0+3 and d0+128..d0+131
    const long base = (long)blockIdx.x * TPB;

    // ---- stage W into shared ----
    #pragma unroll
    for (int i = tid; i < NB * D_MODEL / 4; i += THREADS)
        reinterpret_cast<float4*>(Wsh)[i] = __ldg(reinterpret_cast<const float4*>(mlp_w) + i);
    if (tid < 2) cnts[tid] = 0;
    __syncthreads();

    // ---- classify + compact (1 thread = 1 token) ----
    {
        const long t = base + tid;
        const bool valid = (t < n_tok);
        int tk = 0;
        if (valid) tk = __ldg(token_ids + t);
        const bool act = valid && (tk >= ACT_OFF) && (tk < ACT_OFF + NB);
        const unsigned am = __ballot_sync(0xFFFFFFFFu, act);
        const unsigned im = __ballot_sync(0xFFFFFFFFu, valid && !act);
        int ab = 0, ib = 0;
        if (lane == 0) {
            ab = atomicAdd(&cnts[0], __popc(am));
            ib = atomicAdd(&cnts[1], __popc(im));
        }
        ab = __shfl_sync(0xFFFFFFFFu, ab, 0);
        ib = __shfl_sync(0xFFFFFFFFu, ib, 0);
        const unsigned lt = (1u << lane) - 1u;
        if (act)        alist[ab + __popc(am & lt)] = (unsigned short)tid;
        else if (valid) ilist[ib + __popc(im & lt)] = (unsigned short)tid;
    }
    __syncthreads();
    const int n_act = cnts[0];
    const int n_in  = cnts[1];

    // ---- zero-fill inactive tokens: one warp per token ----
    {
        const float4 z = make_float4(0.f, 0.f, 0.f, 0.f);
        for (int i = warp; i < n_in; i += WARPS) {
            float4* dst = reinterpret_cast<float4*>(out + (base + ilist[i]) * D_MODEL);
            dst[lane]      = z;
            dst[lane + 32] = z;
        }
    }

    if (n_act == 0) return;

    // ---- per-thread channel params (persistent) ----
    const float4 b0  = __ldg(reinterpret_cast<const float4*>(mlp_b    + d0));
    const float4 b1  = __ldg(reinterpret_cast<const float4*>(mlp_b    + 128 + d0));
    const float4 ga0 = __ldg(reinterpret_cast<const float4*>(ln_gamma + d0));
    const float4 ga1 = __ldg(reinterpret_cast<const float4*>(ln_gamma + 128 + d0));
    const float4 be0 = __ldg(reinterpret_cast<const float4*>(ln_beta  + d0));
    const float4 be1 = __ldg(reinterpret_cast<const float4*>(ln_beta  + 128 + d0));

    // ---- active tokens, GTOK per warp per iteration ----
    for (int g = warp * GTOK; g < n_act; g += WARPS * GTOK) {
        const int cnt = min(GTOK, n_act - g);

        long tt[GTOK];
        int  tk[GTOK], aa[GTOK], ss[GTOK];
        #pragma unroll
        for (int j = 0; j < GTOK; j++)
            tt[j] = base + alist[g + (j < cnt ? j : 0)];
        #pragma unroll
        for (int j = 0; j < GTOK; j++) {
            tk[j] = __ldg(token_ids + tt[j]);
            int a = __ldg(action_actors  + tt[j]); aa[j] = a < 0 ? 0 : (a > 1 ? 1 : a);
            int s = __ldg(action_streets + tt[j]); ss[j] = s < 0 ? 0 : (s > 3 ? 3 : s);
        }

        float4 acc0[GTOK], acc1[GTOK];
        #pragma unroll
        for (int j = 0; j < GTOK; j++) { acc0[j] = b0; acc1[j] = b1; }

        // GEMM: masks via uniform __ldg broadcasts (no shuffles), W from smem reused x4
        #pragma unroll
        for (int kc = 0; kc < 4; kc++) {
            float4 m4[GTOK];
            #pragma unroll
            for (int j = 0; j < GTOK; j++)
                m4[j] = __ldg(reinterpret_cast<const float4*>(legal_masks + tt[j] * NB) + kc);
            #pragma unroll
            for (int kk = 0; kk < 4; kk++) {
                const int k = kc * 4 + kk;
                const float4 w0 = *reinterpret_cast<const float4*>(&Wsh[k * D_MODEL + d0]);
                const float4 w1 = *reinterpret_cast<const float4*>(&Wsh[k * D_MODEL + 128 + d0]);
                #pragma unroll
                for (int j = 0; j < GTOK; j++) {
                    const float mk = (&m4[j].x)[kk];
                    acc0[j].x = fmaf(mk, w0.x, acc0[j].x);
                    acc0[j].y = fmaf(mk, w0.y, acc0[j].y);
                    acc0[j].z = fmaf(mk, w0.z, acc0[j].z);
                    acc0[j].w = fmaf(mk, w0.w, acc0[j].w);
                    acc1[j].x = fmaf(mk, w1.x, acc1[j].x);
                    acc1[j].y = fmaf(mk, w1.y, acc1[j].y);
                    acc1[j].z = fmaf(mk, w1.z, acc1[j].z);
                    acc1[j].w = fmaf(mk, w1.w, acc1[j].w);
                }
            }
        }

        // LN stats: 4 tokens' butterflies interleaved (ILP over the shuffle latency)
        float sm[GTOK], sq[GTOK];
        #pragma unroll
        for (int j = 0; j < GTOK; j++) {
            sm[j] = (acc0[j].x + acc0[j].y) + (acc0[j].z + acc0[j].w)
                  + (acc1[j].x + acc1[j].y) + (acc1[j].z + acc1[j].w);
            sq[j] = fmaf(acc0[j].x, acc0[j].x, fmaf(acc0[j].y, acc0[j].y,
                    fmaf(acc0[j].z, acc0[j].z, fmaf(acc0[j].w, acc0[j].w,
                    fmaf(acc1[j].x, acc1[j].x, fmaf(acc1[j].y, acc1[j].y,
                    fmaf(acc1[j].z, acc1[j].z, acc1[j].w * acc1[j].w)))))));
        }
        #pragma unroll
        for (int o = 16; o > 0; o >>= 1) {
            #pragma unroll
            for (int j = 0; j < GTOK; j++) {
                sm[j] += __shfl_xor_sync(0xFFFFFFFFu, sm[j], o);
                sq[j] += __shfl_xor_sync(0xFFFFFFFFu, sq[j], o);
            }
        }

        // epilogue per token
        #pragma unroll
        for (int j = 0; j < GTOK; j++) {
            if (j >= cnt) break;     // warp-uniform
            const float inv = 1.0f / 256.0f;
            const float mu  = sm[j] * inv;
            const float var = fmaf(sq[j], inv, -mu * mu);
            const float rs  = rsqrtf(var + LN_EPS);
            const int aid = tk[j] - ACT_OFF;

            const float4 ea0 = __ldg(reinterpret_cast<const float4*>(actor_emb  + aa[j]  * D_MODEL + d0));
            const float4 ea1 = __ldg(reinterpret_cast<const float4*>(actor_emb  + aa[j]  * D_MODEL + 128 + d0));
            const float4 es0 = __ldg(reinterpret_cast<const float4*>(street_emb + ss[j]  * D_MODEL + d0));
            const float4 es1 = __ldg(reinterpret_cast<const float4*>(street_emb + ss[j]  * D_MODEL + 128 + d0));
            const float4 et0 = __ldg(reinterpret_cast<const float4*>(type_emb   + aid    * D_MODEL + d0));
            const float4 et1 = __ldg(reinterpret_cast<const float4*>(type_emb   + aid    * D_MODEL + 128 + d0));

            float4 r0, r1;
            r0.x = fmaxf(fmaf((acc0[j].x - mu) * rs, ga0.x, be0.x), 0.f) + ea0.x + es0.x + et0.x;
            r0.y = fmaxf(fmaf((acc0[j].y - mu) * rs, ga0.y, be0.y), 0.f) + ea0.y + es0.y + et0.y;
            r0.z = fmaxf(fmaf((acc0[j].z - mu) * rs, ga0.z, be0.z), 0.f) + ea0.z + es0.z + et0.z;
            r0.w = fmaxf(fmaf((acc0[j].w - mu) * rs, ga0.w, be0.w), 0.f) + ea0.w + es0.w + et0.w;
            r1.x = fmaxf(fmaf((acc1[j].x - mu) * rs, ga1.x, be1.x), 0.f) + ea1.x + es1.x + et1.x;
            r1.y = fmaxf(fmaf((acc1[j].y - mu) * rs, ga1.y, be1.y), 0.f) + ea1.y + es1.y + et1.y;
            r1.z = fmaxf(fmaf((acc1[j].z - mu) * rs, ga1.z, be1.z), 0.f) + ea1.z + es1.z + et1.z;
            r1.w = fmaxf(fmaf((acc1[j].w - mu) * rs, ga1.w, be1.w), 0.f) + ea1.w + es1.w + et1.w;

            float4* dst = reinterpret_cast<float4*>(out + tt[j] * D_MODEL);
            dst[lane]      = r0;
            dst[lane + 32] = r1;
        }
    }
}

extern "C" void kernel_launch(void* const* d_in, const int* in_sizes, int n_in,
                              void* d_out, int out_size)
{
    const int*   token_ids   = (const int*)  d_in[0];
    const int*   actors      = (const int*)  d_in[1];
    const int*   streets     = (const int*)  d_in[2];
    const float* legal_masks = (const float*)d_in[3];
    const float* actor_emb   = (const float*)d_in[4];
    const float* street_emb  = (const float*)d_in[5];
    const float* type_emb    = (const float*)d_in[6];
    const float* mlp_w       = (const float*)d_in[7];
    const float* mlp_b       = (const float*)d_in[8];
    const float* ln_gamma    = (const float*)d_in[9];
    const float* ln_beta     = (const float*)d_in[10];
    float* out = (float*)d_out;

    const int n_tok  = in_sizes[0];
    const int blocks = (n_tok + TPB - 1) / TPB;
    action_embedding_kernel<<<blocks, THREADS>>>(
        token_ids, actors, streets, legal_masks,
        actor_emb, street_emb, type_emb,
        mlp_w, mlp_b, ln_gamma, ln_beta,
        out, n_tok);
}